// round 6
// baseline (speedup 1.0000x reference)
#include <cuda_runtime.h>
#include <cuda_bf16.h>
#include <cstdint>

// RingAttention out = softmax(Q K^T) V, B=32, SQ=1024, SKV=8192, D=64, fp32.
// Split-bf16 (hi+lo) flash attention on mma.sync.m16n8k16.
// R6: M=32/warp (4 warps), Q frags hoisted, double-buffered K/V smem,
//     NO register prefetch (stay under 255 regs -> no spills), 1 sync/tile.

#define B_   32
#define SQ_  1024
#define SKV_ 8192
#define D_   64
#define TQ   128
#define TKV  64
#define NT   (SKV_ / TKV)

// smem layout per CTA (96KB):
//   Q:      QH 0..16K, QL 16K..32K   (persist through prologue only)
//   stage0: 32K..64K  (KH +0, KL +8K, VH +16K, VL +24K), 64 rows x 128B each
//   stage1: 64K..96K
#define QH_OFF 0
#define QL_OFF 16384
#define STG0   32768
#define STG_BYTES 32768
#define KH_OFF 0
#define KL_OFF 8192
#define VH_OFF 16384
#define VL_OFF 24576
#define SMEM_BYTES 98304

__device__ __forceinline__ uint32_t smem_u32(const void* p) {
    uint32_t a;
    asm("{ .reg .u64 t; cvta.to.shared.u64 t, %1; cvt.u32.u64 %0, t; }" : "=r"(a) : "l"(p));
    return a;
}
__device__ __forceinline__ void ldsm4(uint32_t r[4], uint32_t a) {
    asm volatile("ldmatrix.sync.aligned.m8n8.x4.shared.b16 {%0,%1,%2,%3}, [%4];"
                 : "=r"(r[0]), "=r"(r[1]), "=r"(r[2]), "=r"(r[3]) : "r"(a));
}
__device__ __forceinline__ void ldsm4t(uint32_t r[4], uint32_t a) {
    asm volatile("ldmatrix.sync.aligned.m8n8.x4.trans.shared.b16 {%0,%1,%2,%3}, [%4];"
                 : "=r"(r[0]), "=r"(r[1]), "=r"(r[2]), "=r"(r[3]) : "r"(a));
}
__device__ __forceinline__ void mma16816(float* c, const uint32_t* a, uint32_t b0, uint32_t b1) {
    asm volatile("mma.sync.aligned.m16n8k16.row.col.f32.bf16.bf16.f32 "
                 "{%0,%1,%2,%3}, {%4,%5,%6,%7}, {%8,%9}, {%0,%1,%2,%3};"
                 : "+f"(c[0]), "+f"(c[1]), "+f"(c[2]), "+f"(c[3])
                 : "r"(a[0]), "r"(a[1]), "r"(a[2]), "r"(a[3]), "r"(b0), "r"(b1));
}
// (x,y) -> bf16x2 hi word + bf16x2 residual word  (x in low half)
__device__ __forceinline__ void split2(float x, float y, uint32_t& h, uint32_t& l) {
    uint32_t hh;
    asm("cvt.rn.bf16x2.f32 %0, %1, %2;" : "=r"(hh) : "f"(y), "f"(x));
    float fx = __uint_as_float(hh << 16);
    float fy = __uint_as_float(hh & 0xffff0000u);
    float rx = x - fx, ry = y - fy;
    asm("cvt.rn.bf16x2.f32 %0, %1, %2;" : "=r"(l) : "f"(ry), "f"(rx));
    h = hh;
}
__device__ __forceinline__ void cvt8(float4 a, float4 b, uint4& h, uint4& l) {
    split2(a.x, a.y, h.x, l.x);
    split2(a.z, a.w, h.y, l.y);
    split2(b.x, b.y, h.z, l.z);
    split2(b.z, b.w, h.w, l.w);
}

__global__ __launch_bounds__(128, 2)
void attn_mma4_kernel(const float* __restrict__ Q,
                      const float* __restrict__ K,
                      const float* __restrict__ V,
                      float* __restrict__ O)
{
    extern __shared__ char sm[];
    const uint32_t smb = smem_u32(sm);
    const int tid  = threadIdx.x;
    const int wid  = tid >> 5;
    const int lane = tid & 31;
    const uint32_t l7  = lane & 7;
    const uint32_t l8  = (lane >> 3) & 1;
    const uint32_t l15 = lane & 15;
    const uint32_t l16 = (uint32_t)lane >> 4;
    const int q0 = blockIdx.x * TQ;
    const int b  = blockIdx.y;

    const float* Kb = K + (size_t)b * SKV_ * D_;
    const float* Vb = V + (size_t)b * SKV_ * D_;

    // per-thread K/V load mapping: row r2 (0..63), half of the 64-float row
    const int r2   = tid >> 1;
    const int half = tid & 1;
    const float4* kp_base = (const float4*)(Kb + (size_t)r2 * D_ + half * 32);
    const float4* vp_base = (const float4*)(Vb + (size_t)r2 * D_ + half * 32);
    const size_t tile_f4 = (size_t)TKV * D_ / 4;

    // ---- prologue: Q -> smem bf16 hi/lo, then frags to regs ----
    {
        const float4* qp = (const float4*)(Q + ((size_t)b * SQ_ + q0 + tid) * D_);
        #pragma unroll
        for (int c = 0; c < 8; ++c) {
            uint4 h, l;
            cvt8(qp[2 * c], qp[2 * c + 1], h, l);
            uint32_t x = (uint32_t)((c ^ (tid & 7)) * 16);
            *(uint4*)(sm + QH_OFF + tid * 128 + x) = h;
            *(uint4*)(sm + QL_OFF + tid * 128 + x) = l;
        }
    }
    __syncthreads();

    uint32_t qh[2][4][4], ql[2][4][4];
    #pragma unroll
    for (int mb = 0; mb < 2; ++mb)
        #pragma unroll
        for (int ks = 0; ks < 4; ++ks) {
            uint32_t a = smb + QH_OFF + (uint32_t)(wid * 32 + mb * 16 + (int)l15) * 128
                             + (((2u * ks + l16) ^ l7) * 16);
            ldsm4(qh[mb][ks], a);
            ldsm4(ql[mb][ks], a + 16384);
        }

    // ---- fill stage 0 with tile 0 (no sync needed vs Q: different region) ----
    {
        char* stg = sm + STG0;
        #pragma unroll
        for (int i = 0; i < 4; ++i) {
            const int c = 4 * half + i;
            uint32_t x = (uint32_t)((c ^ (r2 & 7)) * 16);
            uint4 h, l;
            cvt8(kp_base[2 * i], kp_base[2 * i + 1], h, l);
            *(uint4*)(stg + KH_OFF + r2 * 128 + x) = h;
            *(uint4*)(stg + KL_OFF + r2 * 128 + x) = l;
            cvt8(vp_base[2 * i], vp_base[2 * i + 1], h, l);
            *(uint4*)(stg + VH_OFF + r2 * 128 + x) = h;
            *(uint4*)(stg + VL_OFF + r2 * 128 + x) = l;
        }
    }
    __syncthreads();

    float o[2][8][4];
    #pragma unroll
    for (int mb = 0; mb < 2; ++mb)
        #pragma unroll
        for (int nb = 0; nb < 8; ++nb)
            #pragma unroll
            for (int c = 0; c < 4; ++c) o[mb][nb][c] = 0.f;
    float lsum[2][2] = {{0.f, 0.f}, {0.f, 0.f}};

    for (int t = 0; t < NT; ++t) {
        const uint32_t sbase = smb + STG0 + (uint32_t)((t & 1) * STG_BYTES);

        // ---- compute on stage t&1: per n16-block S -> exp -> P -> O ----
        #pragma unroll
        for (int jp = 0; jp < 4; ++jp) {
            float sa[2][2][4], sb[2][2][4];
            #pragma unroll
            for (int mb = 0; mb < 2; ++mb)
                #pragma unroll
                for (int nh = 0; nh < 2; ++nh)
                    #pragma unroll
                    for (int c = 0; c < 4; ++c) { sa[mb][nh][c] = 0.f; sb[mb][nh][c] = 0.f; }

            #pragma unroll
            for (int ks = 0; ks < 4; ++ks) {
                uint32_t ka = sbase + KH_OFF + (uint32_t)jp * 2048
                                 + (8 * l16 + l7) * 128 + (((2u * ks + l8) ^ l7) * 16);
                uint32_t kh4[4], kl4[4];
                ldsm4(kh4, ka);
                ldsm4(kl4, ka + 8192);
                #pragma unroll
                for (int mb = 0; mb < 2; ++mb) {
                    mma16816(sa[mb][0], qh[mb][ks], kh4[0], kh4[1]);
                    mma16816(sa[mb][1], qh[mb][ks], kh4[2], kh4[3]);
                    mma16816(sb[mb][0], ql[mb][ks], kh4[0], kh4[1]);
                    mma16816(sb[mb][1], ql[mb][ks], kh4[2], kh4[3]);
                    mma16816(sb[mb][0], qh[mb][ks], kl4[0], kl4[1]);
                    mma16816(sb[mb][1], qh[mb][ks], kl4[2], kl4[3]);
                }
            }

            uint32_t ah[2][4], al[2][4];
            #pragma unroll
            for (int mb = 0; mb < 2; ++mb) {
                float e00 = __expf(sa[mb][0][0] + sb[mb][0][0]);
                float e01 = __expf(sa[mb][0][1] + sb[mb][0][1]);
                float e02 = __expf(sa[mb][0][2] + sb[mb][0][2]);
                float e03 = __expf(sa[mb][0][3] + sb[mb][0][3]);
                float e10 = __expf(sa[mb][1][0] + sb[mb][1][0]);
                float e11 = __expf(sa[mb][1][1] + sb[mb][1][1]);
                float e12 = __expf(sa[mb][1][2] + sb[mb][1][2]);
                float e13 = __expf(sa[mb][1][3] + sb[mb][1][3]);
                lsum[mb][0] += (e00 + e01) + (e10 + e11);
                lsum[mb][1] += (e02 + e03) + (e12 + e13);
                split2(e00, e01, ah[mb][0], al[mb][0]);
                split2(e02, e03, ah[mb][1], al[mb][1]);
                split2(e10, e11, ah[mb][2], al[mb][2]);
                split2(e12, e13, ah[mb][3], al[mb][3]);
            }

            #pragma unroll
            for (int np = 0; np < 4; ++np) {
                uint32_t va = sbase + VH_OFF + (uint32_t)jp * 2048
                                 + l15 * 128 + (((2u * np + l16) ^ l7) * 16);
                uint32_t vh4[4], vl4[4];
                ldsm4t(vh4, va);
                ldsm4t(vl4, va + 8192);
                #pragma unroll
                for (int mb = 0; mb < 2; ++mb) {
                    mma16816(o[mb][2 * np],     ah[mb], vh4[0], vh4[1]);
                    mma16816(o[mb][2 * np + 1], ah[mb], vh4[2], vh4[3]);
                    mma16816(o[mb][2 * np],     al[mb], vh4[0], vh4[1]);
                    mma16816(o[mb][2 * np + 1], al[mb], vh4[2], vh4[3]);
                    mma16816(o[mb][2 * np],     ah[mb], vl4[0], vl4[1]);
                    mma16816(o[mb][2 * np + 1], ah[mb], vl4[2], vl4[3]);
                }
            }
        }

        // ---- load tile t+1 into stage (t+1)&1 (LDG hidden by co-resident CTA) ----
        if (t + 1 < NT) {
            char* stg = sm + STG0 + (size_t)(((t + 1) & 1) * STG_BYTES);
            const float4* kp = kp_base + (size_t)(t + 1) * tile_f4;
            const float4* vp = vp_base + (size_t)(t + 1) * tile_f4;
            #pragma unroll
            for (int i = 0; i < 4; ++i) {
                const int c = 4 * half + i;
                uint32_t x = (uint32_t)((c ^ (r2 & 7)) * 16);
                uint4 h, l;
                cvt8(kp[2 * i], kp[2 * i + 1], h, l);
                *(uint4*)(stg + KH_OFF + r2 * 128 + x) = h;
                *(uint4*)(stg + KL_OFF + r2 * 128 + x) = l;
                cvt8(vp[2 * i], vp[2 * i + 1], h, l);
                *(uint4*)(stg + VH_OFF + r2 * 128 + x) = h;
                *(uint4*)(stg + VL_OFF + r2 * 128 + x) = l;
            }
        }
        __syncthreads();
    }

    // ---- epilogue ----
    #pragma unroll
    for (int mb = 0; mb < 2; ++mb)
        #pragma unroll
        for (int h = 0; h < 2; ++h) {
            lsum[mb][h] += __shfl_xor_sync(0xffffffffu, lsum[mb][h], 1);
            lsum[mb][h] += __shfl_xor_sync(0xffffffffu, lsum[mb][h], 2);
        }

    #pragma unroll
    for (int mb = 0; mb < 2; ++mb) {
        const float inv0 = 1.f / lsum[mb][0];
        const float inv1 = 1.f / lsum[mb][1];
        const int row = q0 + wid * 32 + mb * 16 + (lane >> 2);
        float* op0 = O + ((size_t)b * SQ_ + row) * D_ + 2 * (lane & 3);
        float* op1 = op0 + 8 * D_;
        #pragma unroll
        for (int nb = 0; nb < 8; ++nb) {
            *(float2*)(op0 + 8 * nb) = make_float2(o[mb][nb][0] * inv0, o[mb][nb][1] * inv0);
            *(float2*)(op1 + 8 * nb) = make_float2(o[mb][nb][2] * inv1, o[mb][nb][3] * inv1);
        }
    }
}

extern "C" void kernel_launch(void* const* d_in, const int* in_sizes, int n_in,
                              void* d_out, int out_size)
{
    (void)in_sizes; (void)n_in; (void)out_size;
    const float* q = (const float*)d_in[0];
    const float* k = (const float*)d_in[1];
    const float* v = (const float*)d_in[2];
    float* o = (float*)d_out;

    cudaFuncSetAttribute(attn_mma4_kernel,
                         cudaFuncAttributeMaxDynamicSharedMemorySize, SMEM_BYTES);
    dim3 grid(SQ_ / TQ, B_);
    attn_mma4_kernel<<<grid, 128, SMEM_BYTES>>>(q, k, v, o);
}

// round 7
// speedup vs baseline: 1.2417x; 1.2417x over previous
#include <cuda_runtime.h>
#include <cuda_bf16.h>
#include <cstdint>

// RingAttention out = softmax(Q K^T) V, B=32, SQ=1024, SKV=8192, D=64, fp32.
// R7: two kernels.
//   split_kv: K/V fp32 -> bf16 hi/lo, pre-swizzled smem-image blocks in gmem.
//   attn:     R3 tiling (8 warps, M=16/warp, TQ=128, TKV=64), K/V staged via
//             cp.async double-buffer; no conversion work in the hot loop.

#define B_   32
#define SQ_  1024
#define SKV_ 8192
#define D_   64
#define TQ   128
#define TKV  64
#define NT   (SKV_ / TKV)     // 128 tiles per batch

// one 32KB block per (b,t): KH 0, KL 8K, VH 16K, VL 24K; rows*128B, swizzled
#define BLK_BYTES 32768
__device__ uint8_t gKV[(size_t)B_ * NT * BLK_BYTES];   // 128 MB scratch

// attn smem: QH 0..16K, QL 16K..32K, stage0 32K..64K, stage1 64K..96K
#define QH_OFF 0
#define QL_OFF 16384
#define STG0   32768
#define KH_OFF 0
#define KL_OFF 8192
#define VH_OFF 16384
#define VL_OFF 24576
#define SMEM_BYTES 98304

__device__ __forceinline__ uint32_t smem_u32(const void* p) {
    uint32_t a;
    asm("{ .reg .u64 t; cvta.to.shared.u64 t, %1; cvt.u32.u64 %0, t; }" : "=r"(a) : "l"(p));
    return a;
}
__device__ __forceinline__ void ldsm4(uint32_t r[4], uint32_t a) {
    asm volatile("ldmatrix.sync.aligned.m8n8.x4.shared.b16 {%0,%1,%2,%3}, [%4];"
                 : "=r"(r[0]), "=r"(r[1]), "=r"(r[2]), "=r"(r[3]) : "r"(a));
}
__device__ __forceinline__ void ldsm4t(uint32_t r[4], uint32_t a) {
    asm volatile("ldmatrix.sync.aligned.m8n8.x4.trans.shared.b16 {%0,%1,%2,%3}, [%4];"
                 : "=r"(r[0]), "=r"(r[1]), "=r"(r[2]), "=r"(r[3]) : "r"(a));
}
__device__ __forceinline__ void mma16816(float* c, const uint32_t* a, uint32_t b0, uint32_t b1) {
    asm volatile("mma.sync.aligned.m16n8k16.row.col.f32.bf16.bf16.f32 "
                 "{%0,%1,%2,%3}, {%4,%5,%6,%7}, {%8,%9}, {%0,%1,%2,%3};"
                 : "+f"(c[0]), "+f"(c[1]), "+f"(c[2]), "+f"(c[3])
                 : "r"(a[0]), "r"(a[1]), "r"(a[2]), "r"(a[3]), "r"(b0), "r"(b1));
}
__device__ __forceinline__ void split2(float x, float y, uint32_t& h, uint32_t& l) {
    uint32_t hh;
    asm("cvt.rn.bf16x2.f32 %0, %1, %2;" : "=r"(hh) : "f"(y), "f"(x));
    float fx = __uint_as_float(hh << 16);
    float fy = __uint_as_float(hh & 0xffff0000u);
    float rx = x - fx, ry = y - fy;
    asm("cvt.rn.bf16x2.f32 %0, %1, %2;" : "=r"(l) : "f"(ry), "f"(rx));
    h = hh;
}
__device__ __forceinline__ void cvt8(float4 a, float4 b, uint4& h, uint4& l) {
    split2(a.x, a.y, h.x, l.x);
    split2(a.z, a.w, h.y, l.y);
    split2(b.x, b.y, h.z, l.z);
    split2(b.z, b.w, h.w, l.w);
}
#define CP_ASYNC16(dst, src) \
    asm volatile("cp.async.cg.shared.global [%0], [%1], 16;" :: "r"(dst), "l"(src))
#define CP_COMMIT() asm volatile("cp.async.commit_group;" ::: "memory")
#define CP_WAIT0()  asm volatile("cp.async.wait_group 0;" ::: "memory")

// ===================== kernel A: split K/V ======================
__global__ __launch_bounds__(256)
void split_kv_kernel(const float* __restrict__ K, const float* __restrict__ V)
{
    const int t = blockIdx.x;       // kv tile
    const int b = blockIdx.y;       // batch
    const int tid = threadIdx.x;

    const float* Kt = K + ((size_t)b * SKV_ + (size_t)t * TKV) * D_;
    const float* Vt = V + ((size_t)b * SKV_ + (size_t)t * TKV) * D_;
    uint8_t* blk = gKV + ((size_t)b * NT + t) * BLK_BYTES;

    #pragma unroll
    for (int uu = 0; uu < 2; ++uu) {
        const int u = tid + 256 * uu;   // 0..511 = 64 rows x 8 chunks
        const int r = u >> 3;
        const int c = u & 7;
        const uint32_t off = (uint32_t)r * 128 + (uint32_t)((c ^ (r & 7)) * 16);
        const float4* kp = (const float4*)(Kt + (size_t)r * D_ + c * 8);
        const float4* vp = (const float4*)(Vt + (size_t)r * D_ + c * 8);
        uint4 h, l;
        cvt8(kp[0], kp[1], h, l);
        *(uint4*)(blk + KH_OFF + off) = h;
        *(uint4*)(blk + KL_OFF + off) = l;
        cvt8(vp[0], vp[1], h, l);
        *(uint4*)(blk + VH_OFF + off) = h;
        *(uint4*)(blk + VL_OFF + off) = l;
    }
}

// ===================== kernel B: attention ======================
__global__ __launch_bounds__(256, 2)
void attn_mma5_kernel(const float* __restrict__ Q, float* __restrict__ O)
{
    extern __shared__ char sm[];
    const uint32_t smb = smem_u32(sm);
    const int tid  = threadIdx.x;
    const int wid  = tid >> 5;
    const int lane = tid & 31;
    const uint32_t l7  = lane & 7;
    const uint32_t l8  = (lane >> 3) & 1;
    const uint32_t l15 = lane & 15;
    const uint32_t l16 = (uint32_t)lane >> 4;
    const int q0 = blockIdx.x * TQ;
    const int b  = blockIdx.y;

    const uint8_t* blk0 = gKV + (size_t)b * NT * BLK_BYTES;

    // ---- prologue: Q -> smem bf16 hi/lo (persistent region) ----
    {
        const int r = tid >> 1, half = tid & 1;
        const float4* qp = (const float4*)(Q + ((size_t)b * SQ_ + q0 + r) * D_ + half * 32);
        #pragma unroll
        for (int c = 0; c < 4; ++c) {
            uint4 h, l;
            cvt8(qp[2 * c], qp[2 * c + 1], h, l);
            const int cc = 4 * half + c;
            uint32_t x = (uint32_t)((cc ^ (r & 7)) * 16);
            *(uint4*)(sm + QH_OFF + r * 128 + x) = h;
            *(uint4*)(sm + QL_OFF + r * 128 + x) = l;
        }
    }

    // ---- stage 0: cp.async tile 0 ----
    {
        const uint32_t dst = smb + STG0 + (uint32_t)tid * 16;
        const uint8_t* src = blk0 + (size_t)tid * 16;
        #pragma unroll
        for (int i = 0; i < 8; ++i)
            CP_ASYNC16(dst + i * 4096, src + i * 4096);
        CP_COMMIT();
    }

    // per-warp fragment address components (R3 mapping)
    const int wrow = wid * 16;
    const uint32_t qrowb = (uint32_t)(wrow + (int)l15) * 128;
    const uint32_t krowb = (8 * l16 + l7) * 128;
    const uint32_t vrowb = l15 * 128;

    float o[8][4];
    #pragma unroll
    for (int i = 0; i < 8; ++i)
        #pragma unroll
        for (int j = 0; j < 4; ++j) o[i][j] = 0.f;
    float lsum0 = 0.f, lsum1 = 0.f;

    for (int t = 0; t < NT; ++t) {
        CP_WAIT0();          // stage t&1 landed
        __syncthreads();     // all warps done with compute(t-1); other stage free

        if (t + 1 < NT) {    // copy t+1 overlaps compute(t)
            const uint32_t dst = smb + STG0 + (uint32_t)(((t + 1) & 1) * BLK_BYTES)
                                 + (uint32_t)tid * 16;
            const uint8_t* src = blk0 + (size_t)(t + 1) * BLK_BYTES + (size_t)tid * 16;
            #pragma unroll
            for (int i = 0; i < 8; ++i)
                CP_ASYNC16(dst + i * 4096, src + i * 4096);
            CP_COMMIT();
        }

        const uint32_t sbase = smb + STG0 + (uint32_t)((t & 1) * BLK_BYTES);

        // ---- S = Qh Kh^T + Ql Kh^T + Qh Kl^T  (16x64 per warp) ----
        float s[8][4];
        #pragma unroll
        for (int i = 0; i < 8; ++i)
            #pragma unroll
            for (int j = 0; j < 4; ++j) s[i][j] = 0.f;

        #pragma unroll
        for (int ks = 0; ks < 4; ++ks) {
            uint32_t qh[4], ql[4];
            const uint32_t qx = ((2 * ks + l16) ^ l7) * 16;
            ldsm4(qh, smb + QH_OFF + qrowb + qx);
            ldsm4(ql, smb + QL_OFF + qrowb + qx);
            const uint32_t kx = ((2 * ks + l8) ^ l7) * 16;
            #pragma unroll
            for (int jp = 0; jp < 4; ++jp) {
                uint32_t kb[4];
                ldsm4(kb, sbase + KH_OFF + krowb + (uint32_t)jp * 2048 + kx);
                mma16816(s[2 * jp],     qh, kb[0], kb[1]);
                mma16816(s[2 * jp + 1], qh, kb[2], kb[3]);
                mma16816(s[2 * jp],     ql, kb[0], kb[1]);
                mma16816(s[2 * jp + 1], ql, kb[2], kb[3]);
            }
            #pragma unroll
            for (int jp = 0; jp < 4; ++jp) {
                uint32_t kb[4];
                ldsm4(kb, sbase + KL_OFF + krowb + (uint32_t)jp * 2048 + kx);
                mma16816(s[2 * jp],     qh, kb[0], kb[1]);
                mma16816(s[2 * jp + 1], qh, kb[2], kb[3]);
            }
        }

        // ---- P = exp(S) (fixed max 0), split to bf16 hi/lo A-frags ----
        uint32_t ph[8][2], pl[8][2];
        #pragma unroll
        for (int j = 0; j < 8; ++j) {
            float p0 = __expf(s[j][0]);
            float p1 = __expf(s[j][1]);
            float p2 = __expf(s[j][2]);
            float p3 = __expf(s[j][3]);
            lsum0 += p0 + p1;
            lsum1 += p2 + p3;
            split2(p0, p1, ph[j][0], pl[j][0]);
            split2(p2, p3, ph[j][1], pl[j][1]);
        }

        // ---- O += Ph Vh + Pl Vh + Ph Vl ----
        #pragma unroll
        for (int kb = 0; kb < 4; ++kb) {
            uint32_t ah[4] = { ph[2 * kb][0], ph[2 * kb][1], ph[2 * kb + 1][0], ph[2 * kb + 1][1] };
            uint32_t al[4] = { pl[2 * kb][0], pl[2 * kb][1], pl[2 * kb + 1][0], pl[2 * kb + 1][1] };
            const uint32_t vb_row = vrowb + (uint32_t)kb * 2048;
            #pragma unroll
            for (int np = 0; np < 4; ++np) {
                uint32_t vb[4];
                ldsm4t(vb, sbase + VH_OFF + vb_row + (((2 * np + l16) ^ l7) * 16));
                mma16816(o[2 * np],     ah, vb[0], vb[1]);
                mma16816(o[2 * np + 1], ah, vb[2], vb[3]);
                mma16816(o[2 * np],     al, vb[0], vb[1]);
                mma16816(o[2 * np + 1], al, vb[2], vb[3]);
            }
            #pragma unroll
            for (int np = 0; np < 4; ++np) {
                uint32_t vb[4];
                ldsm4t(vb, sbase + VL_OFF + vb_row + (((2 * np + l16) ^ l7) * 16));
                mma16816(o[2 * np],     ah, vb[0], vb[1]);
                mma16816(o[2 * np + 1], ah, vb[2], vb[3]);
            }
        }
    }

    // ---- epilogue: quad-reduce row sums, normalize, store ----
    lsum0 += __shfl_xor_sync(0xffffffffu, lsum0, 1);
    lsum0 += __shfl_xor_sync(0xffffffffu, lsum0, 2);
    lsum1 += __shfl_xor_sync(0xffffffffu, lsum1, 1);
    lsum1 += __shfl_xor_sync(0xffffffffu, lsum1, 2);
    const float inv0 = 1.f / lsum0;
    const float inv1 = 1.f / lsum1;

    const int grow = q0 + wrow + (lane >> 2);
    float* op0 = O + ((size_t)b * SQ_ + grow) * D_ + 2 * (lane & 3);
    float* op1 = op0 + 8 * D_;
    #pragma unroll
    for (int nb = 0; nb < 8; ++nb) {
        *(float2*)(op0 + 8 * nb) = make_float2(o[nb][0] * inv0, o[nb][1] * inv0);
        *(float2*)(op1 + 8 * nb) = make_float2(o[nb][2] * inv1, o[nb][3] * inv1);
    }
}

extern "C" void kernel_launch(void* const* d_in, const int* in_sizes, int n_in,
                              void* d_out, int out_size)
{
    (void)in_sizes; (void)n_in; (void)out_size;
    const float* q = (const float*)d_in[0];
    const float* k = (const float*)d_in[1];
    const float* v = (const float*)d_in[2];
    float* o = (float*)d_out;

    dim3 sgrid(NT, B_);
    split_kv_kernel<<<sgrid, 256>>>(k, v);

    cudaFuncSetAttribute(attn_mma5_kernel,
                         cudaFuncAttributeMaxDynamicSharedMemorySize, SMEM_BYTES);
    dim3 grid(SQ_ / TQ, B_);
    attn_mma5_kernel<<<grid, 256, SMEM_BYTES>>>(q, o);
}

// round 8
// speedup vs baseline: 1.6329x; 1.3151x over previous
#include <cuda_runtime.h>
#include <cuda_fp16.h>
#include <cstdint>
#include <math.h>

// RingAttention out = softmax(Q K^T) V, B=32, SQ=1024, SKV=8192, D=64, fp32.
// R8: fp16 pipeline + online row max.
//   S = QhKh + QlKh + QhKl (fp16 split, fp32 accum)  -- 96 MMA/warp-tile
//   P = exp(S - m) in [0,1] -> single fp16; V single fp16 -> O in ONE pass
//                                                       -- 32 MMA/warp-tile
//   split_kv pre-converts K (hi+lo) and V (hi) into swizzled smem-image blocks.

#define B_   32
#define SQ_  1024
#define SKV_ 8192
#define D_   64
#define TQ   128
#define TKV  64
#define NT   (SKV_ / TKV)

// per-(b,t) block: KH 0..8K, KL 8K..16K, VH 16K..24K (64 rows x 128B, swizzled)
#define BLK_BYTES 24576
__device__ uint8_t gKV[(size_t)B_ * NT * BLK_BYTES];   // 96 MB scratch

// attn smem: QH 0..16K, QL 16K..32K, stage0 32K..56K, stage1 56K..80K
#define QH_OFF 0
#define QL_OFF 16384
#define STG0   32768
#define KH_OFF 0
#define KL_OFF 8192
#define VH_OFF 16384
#define SMEM_BYTES (32768 + 2 * BLK_BYTES)   // 81920

__device__ __forceinline__ uint32_t smem_u32(const void* p) {
    uint32_t a;
    asm("{ .reg .u64 t; cvta.to.shared.u64 t, %1; cvt.u32.u64 %0, t; }" : "=r"(a) : "l"(p));
    return a;
}
__device__ __forceinline__ void ldsm4(uint32_t r[4], uint32_t a) {
    asm volatile("ldmatrix.sync.aligned.m8n8.x4.shared.b16 {%0,%1,%2,%3}, [%4];"
                 : "=r"(r[0]), "=r"(r[1]), "=r"(r[2]), "=r"(r[3]) : "r"(a));
}
__device__ __forceinline__ void ldsm4t(uint32_t r[4], uint32_t a) {
    asm volatile("ldmatrix.sync.aligned.m8n8.x4.trans.shared.b16 {%0,%1,%2,%3}, [%4];"
                 : "=r"(r[0]), "=r"(r[1]), "=r"(r[2]), "=r"(r[3]) : "r"(a));
}
__device__ __forceinline__ void mma16816h(float* c, const uint32_t* a, uint32_t b0, uint32_t b1) {
    asm volatile("mma.sync.aligned.m16n8k16.row.col.f32.f16.f16.f32 "
                 "{%0,%1,%2,%3}, {%4,%5,%6,%7}, {%8,%9}, {%0,%1,%2,%3};"
                 : "+f"(c[0]), "+f"(c[1]), "+f"(c[2]), "+f"(c[3])
                 : "r"(a[0]), "r"(a[1]), "r"(a[2]), "r"(a[3]), "r"(b0), "r"(b1));
}
// pack (x,y) -> f16x2 (x low)
__device__ __forceinline__ uint32_t packh(float x, float y) {
    __half2 h = __floats2half2_rn(x, y);
    return *reinterpret_cast<uint32_t*>(&h);
}
// (x,y) -> f16x2 hi + f16x2 residual
__device__ __forceinline__ void split2h(float x, float y, uint32_t& h, uint32_t& l) {
    __half2 hp = __floats2half2_rn(x, y);
    float rx = x - __half2float(__low2half(hp));
    float ry = y - __half2float(__high2half(hp));
    __half2 lp = __floats2half2_rn(rx, ry);
    h = *reinterpret_cast<uint32_t*>(&hp);
    l = *reinterpret_cast<uint32_t*>(&lp);
}
__device__ __forceinline__ void cvt8h(float4 a, float4 b, uint4& h, uint4& l) {
    split2h(a.x, a.y, h.x, l.x);
    split2h(a.z, a.w, h.y, l.y);
    split2h(b.x, b.y, h.z, l.z);
    split2h(b.z, b.w, h.w, l.w);
}
__device__ __forceinline__ uint4 cvt8h1(float4 a, float4 b) {
    uint4 h;
    h.x = packh(a.x, a.y);
    h.y = packh(a.z, a.w);
    h.z = packh(b.x, b.y);
    h.w = packh(b.z, b.w);
    return h;
}
#define CP_ASYNC16(dst, src) \
    asm volatile("cp.async.cg.shared.global [%0], [%1], 16;" :: "r"(dst), "l"(src))
#define CP_COMMIT() asm volatile("cp.async.commit_group;" ::: "memory")
#define CP_WAIT0()  asm volatile("cp.async.wait_group 0;" ::: "memory")

// ===================== kernel A: split K/V ======================
__global__ __launch_bounds__(256)
void split_kv_kernel(const float* __restrict__ K, const float* __restrict__ V)
{
    const int t = blockIdx.x;
    const int b = blockIdx.y;
    const int tid = threadIdx.x;

    const float* Kt = K + ((size_t)b * SKV_ + (size_t)t * TKV) * D_;
    const float* Vt = V + ((size_t)b * SKV_ + (size_t)t * TKV) * D_;
    uint8_t* blk = gKV + ((size_t)b * NT + t) * BLK_BYTES;

    #pragma unroll
    for (int uu = 0; uu < 2; ++uu) {
        const int u = tid + 256 * uu;       // 0..511 = 64 rows x 8 chunks
        const int r = u >> 3;
        const int c = u & 7;
        const uint32_t off = (uint32_t)r * 128 + (uint32_t)((c ^ (r & 7)) * 16);
        const float4* kp = (const float4*)(Kt + (size_t)r * D_ + c * 8);
        const float4* vp = (const float4*)(Vt + (size_t)r * D_ + c * 8);
        uint4 h, l;
        cvt8h(kp[0], kp[1], h, l);
        *(uint4*)(blk + KH_OFF + off) = h;
        *(uint4*)(blk + KL_OFF + off) = l;
        *(uint4*)(blk + VH_OFF + off) = cvt8h1(vp[0], vp[1]);
    }
}

// ===================== kernel B: attention ======================
__global__ __launch_bounds__(256, 2)
void attn_mma6_kernel(const float* __restrict__ Q, float* __restrict__ O)
{
    extern __shared__ char sm[];
    const uint32_t smb = smem_u32(sm);
    const int tid  = threadIdx.x;
    const int wid  = tid >> 5;
    const int lane = tid & 31;
    const uint32_t l7  = lane & 7;
    const uint32_t l8  = (lane >> 3) & 1;
    const uint32_t l15 = lane & 15;
    const uint32_t l16 = (uint32_t)lane >> 4;
    const int q0 = blockIdx.x * TQ;
    const int b  = blockIdx.y;

    const uint8_t* blk0 = gKV + (size_t)b * NT * BLK_BYTES;

    // ---- prologue: Q -> smem fp16 hi/lo ----
    {
        const int r = tid >> 1, half = tid & 1;
        const float4* qp = (const float4*)(Q + ((size_t)b * SQ_ + q0 + r) * D_ + half * 32);
        #pragma unroll
        for (int c = 0; c < 4; ++c) {
            uint4 h, l;
            cvt8h(qp[2 * c], qp[2 * c + 1], h, l);
            const int cc = 4 * half + c;
            uint32_t x = (uint32_t)((cc ^ (r & 7)) * 16);
            *(uint4*)(sm + QH_OFF + r * 128 + x) = h;
            *(uint4*)(sm + QL_OFF + r * 128 + x) = l;
        }
    }

    // ---- stage 0: cp.async tile 0 (24KB = 6 x 16B per thread) ----
    {
        const uint32_t dst = smb + STG0 + (uint32_t)tid * 16;
        const uint8_t* src = blk0 + (size_t)tid * 16;
        #pragma unroll
        for (int i = 0; i < 6; ++i)
            CP_ASYNC16(dst + i * 4096, src + i * 4096);
        CP_COMMIT();
    }

    const int wrow = wid * 16;
    const uint32_t qrowb = (uint32_t)(wrow + (int)l15) * 128;
    const uint32_t krowb = (8 * l16 + l7) * 128;
    const uint32_t vrowb = l15 * 128;

    float o[8][4];
    #pragma unroll
    for (int i = 0; i < 8; ++i)
        #pragma unroll
        for (int j = 0; j < 4; ++j) o[i][j] = 0.f;
    float lsum0 = 0.f, lsum1 = 0.f;
    float m0 = -1e30f, m1 = -1e30f;

    for (int t = 0; t < NT; ++t) {
        CP_WAIT0();
        __syncthreads();

        if (t + 1 < NT) {
            const uint32_t dst = smb + STG0 + (uint32_t)(((t + 1) & 1) * BLK_BYTES)
                                 + (uint32_t)tid * 16;
            const uint8_t* src = blk0 + (size_t)(t + 1) * BLK_BYTES + (size_t)tid * 16;
            #pragma unroll
            for (int i = 0; i < 6; ++i)
                CP_ASYNC16(dst + i * 4096, src + i * 4096);
            CP_COMMIT();
        }

        const uint32_t sbase = smb + STG0 + (uint32_t)((t & 1) * BLK_BYTES);

        // ---- S = Qh Kh^T + Ql Kh^T + Qh Kl^T (fp16, fp32 accum) ----
        float s[8][4];
        #pragma unroll
        for (int i = 0; i < 8; ++i)
            #pragma unroll
            for (int j = 0; j < 4; ++j) s[i][j] = 0.f;

        #pragma unroll
        for (int ks = 0; ks < 4; ++ks) {
            uint32_t qh[4], ql[4];
            const uint32_t qx = ((2 * ks + l16) ^ l7) * 16;
            ldsm4(qh, smb + QH_OFF + qrowb + qx);
            ldsm4(ql, smb + QL_OFF + qrowb + qx);
            const uint32_t kx = ((2 * ks + l8) ^ l7) * 16;
            #pragma unroll
            for (int jp = 0; jp < 4; ++jp) {
                uint32_t kb[4];
                ldsm4(kb, sbase + KH_OFF + krowb + (uint32_t)jp * 2048 + kx);
                mma16816h(s[2 * jp],     qh, kb[0], kb[1]);
                mma16816h(s[2 * jp + 1], qh, kb[2], kb[3]);
                mma16816h(s[2 * jp],     ql, kb[0], kb[1]);
                mma16816h(s[2 * jp + 1], ql, kb[2], kb[3]);
            }
            #pragma unroll
            for (int jp = 0; jp < 4; ++jp) {
                uint32_t kb[4];
                ldsm4(kb, sbase + KL_OFF + krowb + (uint32_t)jp * 2048 + kx);
                mma16816h(s[2 * jp],     qh, kb[0], kb[1]);
                mma16816h(s[2 * jp + 1], qh, kb[2], kb[3]);
            }
        }

        // ---- online max + P = exp(S - m) in fp16 ----
        float m0t = s[0][0], m1t = s[0][2];
        #pragma unroll
        for (int j = 0; j < 8; ++j) {
            m0t = fmaxf(m0t, fmaxf(s[j][0], s[j][1]));
            m1t = fmaxf(m1t, fmaxf(s[j][2], s[j][3]));
        }
        m0t = fmaxf(m0t, __shfl_xor_sync(0xffffffffu, m0t, 1));
        m0t = fmaxf(m0t, __shfl_xor_sync(0xffffffffu, m0t, 2));
        m1t = fmaxf(m1t, __shfl_xor_sync(0xffffffffu, m1t, 1));
        m1t = fmaxf(m1t, __shfl_xor_sync(0xffffffffu, m1t, 2));

        const float m0n = fmaxf(m0, m0t);
        const float m1n = fmaxf(m1, m1t);
        const float a0 = __expf(m0 - m0n);
        const float a1 = __expf(m1 - m1n);
        m0 = m0n; m1 = m1n;
        lsum0 *= a0; lsum1 *= a1;
        #pragma unroll
        for (int nb = 0; nb < 8; ++nb) {
            o[nb][0] *= a0; o[nb][1] *= a0;
            o[nb][2] *= a1; o[nb][3] *= a1;
        }

        uint32_t ph[8][2];
        #pragma unroll
        for (int j = 0; j < 8; ++j) {
            float e0 = __expf(s[j][0] - m0n);
            float e1 = __expf(s[j][1] - m0n);
            float e2 = __expf(s[j][2] - m1n);
            float e3 = __expf(s[j][3] - m1n);
            lsum0 += e0 + e1;
            lsum1 += e2 + e3;
            ph[j][0] = packh(e0, e1);
            ph[j][1] = packh(e2, e3);
        }

        // ---- O += P V  (single fp16 pass) ----
        #pragma unroll
        for (int kb = 0; kb < 4; ++kb) {
            uint32_t ah[4] = { ph[2 * kb][0], ph[2 * kb][1],
                               ph[2 * kb + 1][0], ph[2 * kb + 1][1] };
            const uint32_t vb_row = vrowb + (uint32_t)kb * 2048;
            #pragma unroll
            for (int np = 0; np < 4; ++np) {
                uint32_t vb[4];
                ldsm4t(vb, sbase + VH_OFF + vb_row + (((2 * np + l16) ^ l7) * 16));
                mma16816h(o[2 * np],     ah, vb[0], vb[1]);
                mma16816h(o[2 * np + 1], ah, vb[2], vb[3]);
            }
        }
    }

    // ---- epilogue: quad-reduce row sums, normalize, store ----
    lsum0 += __shfl_xor_sync(0xffffffffu, lsum0, 1);
    lsum0 += __shfl_xor_sync(0xffffffffu, lsum0, 2);
    lsum1 += __shfl_xor_sync(0xffffffffu, lsum1, 1);
    lsum1 += __shfl_xor_sync(0xffffffffu, lsum1, 2);
    const float inv0 = 1.f / lsum0;
    const float inv1 = 1.f / lsum1;

    const int grow = q0 + wrow + (lane >> 2);
    float* op0 = O + ((size_t)b * SQ_ + grow) * D_ + 2 * (lane & 3);
    float* op1 = op0 + 8 * D_;
    #pragma unroll
    for (int nb = 0; nb < 8; ++nb) {
        *(float2*)(op0 + 8 * nb) = make_float2(o[nb][0] * inv0, o[nb][1] * inv0);
        *(float2*)(op1 + 8 * nb) = make_float2(o[nb][2] * inv1, o[nb][3] * inv1);
    }
}

extern "C" void kernel_launch(void* const* d_in, const int* in_sizes, int n_in,
                              void* d_out, int out_size)
{
    (void)in_sizes; (void)n_in; (void)out_size;
    const float* q = (const float*)d_in[0];
    const float* k = (const float*)d_in[1];
    const float* v = (const float*)d_in[2];
    float* o = (float*)d_out;

    dim3 sgrid(NT, B_);
    split_kv_kernel<<<sgrid, 256>>>(k, v);

    cudaFuncSetAttribute(attn_mma6_kernel,
                         cudaFuncAttributeMaxDynamicSharedMemorySize, SMEM_BYTES);
    dim3 grid(SQ_ / TQ, B_);
    attn_mma6_kernel<<<grid, 256, SMEM_BYTES>>>(q, o);
}

// round 9
// speedup vs baseline: 1.7163x; 1.0511x over previous
#include <cuda_runtime.h>
#include <cuda_fp16.h>
#include <cstdint>
#include <math.h>

// RingAttention out = softmax(Q K^T) V, B=32, SQ=1024, SKV=8192, D=64, fp32.
// R9: fp16 pipeline, M=32/warp (4 warps, TQ=128), Qh frags hoisted,
//     online max with log2-domain exp (ex2.approx), pre-split K/V + cp.async.

#define B_   32
#define SQ_  1024
#define SKV_ 8192
#define D_   64
#define TQ   128
#define TKV  64
#define NT   (SKV_ / TKV)

// per-(b,t) block: KH 0..8K, KL 8K..16K, VH 16K..24K (64 rows x 128B, swizzled)
#define BLK_BYTES 24576
__device__ uint8_t gKV[(size_t)B_ * NT * BLK_BYTES];   // 96 MB scratch

// attn smem: QH 0..16K (prologue only), QL 16K..32K (persistent),
//            stage0 32K..56K, stage1 56K..80K
#define QH_OFF 0
#define QL_OFF 16384
#define STG0   32768
#define KH_OFF 0
#define KL_OFF 8192
#define VH_OFF 16384
#define SMEM_BYTES (32768 + 2 * BLK_BYTES)   // 81920

__device__ __forceinline__ uint32_t smem_u32(const void* p) {
    uint32_t a;
    asm("{ .reg .u64 t; cvta.to.shared.u64 t, %1; cvt.u32.u64 %0, t; }" : "=r"(a) : "l"(p));
    return a;
}
__device__ __forceinline__ void ldsm4(uint32_t r[4], uint32_t a) {
    asm volatile("ldmatrix.sync.aligned.m8n8.x4.shared.b16 {%0,%1,%2,%3}, [%4];"
                 : "=r"(r[0]), "=r"(r[1]), "=r"(r[2]), "=r"(r[3]) : "r"(a));
}
__device__ __forceinline__ void ldsm4t(uint32_t r[4], uint32_t a) {
    asm volatile("ldmatrix.sync.aligned.m8n8.x4.trans.shared.b16 {%0,%1,%2,%3}, [%4];"
                 : "=r"(r[0]), "=r"(r[1]), "=r"(r[2]), "=r"(r[3]) : "r"(a));
}
__device__ __forceinline__ void mma16816h(float* c, const uint32_t* a, uint32_t b0, uint32_t b1) {
    asm volatile("mma.sync.aligned.m16n8k16.row.col.f32.f16.f16.f32 "
                 "{%0,%1,%2,%3}, {%4,%5,%6,%7}, {%8,%9}, {%0,%1,%2,%3};"
                 : "+f"(c[0]), "+f"(c[1]), "+f"(c[2]), "+f"(c[3])
                 : "r"(a[0]), "r"(a[1]), "r"(a[2]), "r"(a[3]), "r"(b0), "r"(b1));
}
__device__ __forceinline__ float ex2f(float x) {
    float r;
    asm("ex2.approx.f32 %0, %1;" : "=f"(r) : "f"(x));
    return r;
}
__device__ __forceinline__ uint32_t packh(float x, float y) {
    __half2 h = __floats2half2_rn(x, y);
    return *reinterpret_cast<uint32_t*>(&h);
}
__device__ __forceinline__ void split2h(float x, float y, uint32_t& h, uint32_t& l) {
    __half2 hp = __floats2half2_rn(x, y);
    float rx = x - __half2float(__low2half(hp));
    float ry = y - __half2float(__high2half(hp));
    __half2 lp = __floats2half2_rn(rx, ry);
    h = *reinterpret_cast<uint32_t*>(&hp);
    l = *reinterpret_cast<uint32_t*>(&lp);
}
__device__ __forceinline__ void cvt8h(float4 a, float4 b, uint4& h, uint4& l) {
    split2h(a.x, a.y, h.x, l.x);
    split2h(a.z, a.w, h.y, l.y);
    split2h(b.x, b.y, h.z, l.z);
    split2h(b.z, b.w, h.w, l.w);
}
__device__ __forceinline__ uint4 cvt8h1(float4 a, float4 b) {
    uint4 h;
    h.x = packh(a.x, a.y);
    h.y = packh(a.z, a.w);
    h.z = packh(b.x, b.y);
    h.w = packh(b.z, b.w);
    return h;
}
#define CP_ASYNC16(dst, src) \
    asm volatile("cp.async.cg.shared.global [%0], [%1], 16;" :: "r"(dst), "l"(src))
#define CP_COMMIT() asm volatile("cp.async.commit_group;" ::: "memory")
#define CP_WAIT0()  asm volatile("cp.async.wait_group 0;" ::: "memory")

// ===================== kernel A: split K/V ======================
__global__ __launch_bounds__(256)
void split_kv_kernel(const float* __restrict__ K, const float* __restrict__ V)
{
    const int t = blockIdx.x;
    const int b = blockIdx.y;
    const int tid = threadIdx.x;

    const float* Kt = K + ((size_t)b * SKV_ + (size_t)t * TKV) * D_;
    const float* Vt = V + ((size_t)b * SKV_ + (size_t)t * TKV) * D_;
    uint8_t* blk = gKV + ((size_t)b * NT + t) * BLK_BYTES;

    #pragma unroll
    for (int uu = 0; uu < 2; ++uu) {
        const int u = tid + 256 * uu;       // 0..511 = 64 rows x 8 chunks
        const int r = u >> 3;
        const int c = u & 7;
        const uint32_t off = (uint32_t)r * 128 + (uint32_t)((c ^ (r & 7)) * 16);
        const float4* kp = (const float4*)(Kt + (size_t)r * D_ + c * 8);
        const float4* vp = (const float4*)(Vt + (size_t)r * D_ + c * 8);
        uint4 h, l;
        cvt8h(kp[0], kp[1], h, l);
        *(uint4*)(blk + KH_OFF + off) = h;
        *(uint4*)(blk + KL_OFF + off) = l;
        *(uint4*)(blk + VH_OFF + off) = cvt8h1(vp[0], vp[1]);
    }
}

// ===================== kernel B: attention ======================
__global__ __launch_bounds__(128, 2)
void attn_mma7_kernel(const float* __restrict__ Q, float* __restrict__ O)
{
    extern __shared__ char sm[];
    const uint32_t smb = smem_u32(sm);
    const int tid  = threadIdx.x;
    const int wid  = tid >> 5;
    const int lane = tid & 31;
    const uint32_t l7  = lane & 7;
    const uint32_t l8  = (lane >> 3) & 1;
    const uint32_t l15 = lane & 15;
    const uint32_t l16 = (uint32_t)lane >> 4;
    const int q0 = blockIdx.x * TQ;
    const int b  = blockIdx.y;

    const uint8_t* blk0 = gKV + (size_t)b * NT * BLK_BYTES;

    // ---- prologue: Q * log2(e) -> smem fp16 hi/lo (one 64-float row/thread) ----
    {
        const float4* qp = (const float4*)(Q + ((size_t)b * SQ_ + q0 + tid) * D_);
        const float LG2E = 1.4426950408889634f;
        #pragma unroll
        for (int c = 0; c < 8; ++c) {
            float4 f0 = qp[2 * c], f1 = qp[2 * c + 1];
            f0.x *= LG2E; f0.y *= LG2E; f0.z *= LG2E; f0.w *= LG2E;
            f1.x *= LG2E; f1.y *= LG2E; f1.z *= LG2E; f1.w *= LG2E;
            uint4 h, l;
            cvt8h(f0, f1, h, l);
            uint32_t x = (uint32_t)((c ^ (tid & 7)) * 16);
            *(uint4*)(sm + QH_OFF + tid * 128 + x) = h;
            *(uint4*)(sm + QL_OFF + tid * 128 + x) = l;
        }
    }
    __syncthreads();

    // hoist Qh fragments (Ql stays in smem, read per tile)
    uint32_t qhr[2][4][4];                 // [mb][k16][frag]
    #pragma unroll
    for (int mb = 0; mb < 2; ++mb)
        #pragma unroll
        for (int ks = 0; ks < 4; ++ks) {
            uint32_t a = smb + QH_OFF
                       + (uint32_t)(wid * 32 + mb * 16 + (int)l15) * 128
                       + (((2u * ks + l16) ^ l7) * 16);
            ldsm4(qhr[mb][ks], a);
        }

    // ---- stage 0: cp.async tile 0 (24KB = 12 x 16B per thread) ----
    {
        const uint32_t dst = smb + STG0 + (uint32_t)tid * 16;
        const uint8_t* src = blk0 + (size_t)tid * 16;
        #pragma unroll
        for (int i = 0; i < 12; ++i)
            CP_ASYNC16(dst + i * 2048, src + i * 2048);
        CP_COMMIT();
    }

    const uint32_t krowb = (8 * l16 + l7) * 128;
    const uint32_t vrowb = l15 * 128;
    const uint32_t qlrow = (uint32_t)(wid * 32 + (int)l15) * 128;   // +mb*2048

    float o[2][8][4];
    #pragma unroll
    for (int mb = 0; mb < 2; ++mb)
        #pragma unroll
        for (int nb = 0; nb < 8; ++nb)
            #pragma unroll
            for (int c = 0; c < 4; ++c) o[mb][nb][c] = 0.f;
    float lsum[2][2] = {{0.f, 0.f}, {0.f, 0.f}};
    float m[2][2] = {{-1e30f, -1e30f}, {-1e30f, -1e30f}};

    for (int t = 0; t < NT; ++t) {
        CP_WAIT0();
        __syncthreads();

        if (t + 1 < NT) {
            const uint32_t dst = smb + STG0 + (uint32_t)(((t + 1) & 1) * BLK_BYTES)
                                 + (uint32_t)tid * 16;
            const uint8_t* src = blk0 + (size_t)(t + 1) * BLK_BYTES + (size_t)tid * 16;
            #pragma unroll
            for (int i = 0; i < 12; ++i)
                CP_ASYNC16(dst + i * 2048, src + i * 2048);
            CP_COMMIT();
        }

        const uint32_t sbase = smb + STG0 + (uint32_t)((t & 1) * BLK_BYTES);

        // ---- S (32x64 per warp): Qh Kh + Ql Kh + Qh Kl, fp32 accum ----
        float s[2][8][4];
        #pragma unroll
        for (int mb = 0; mb < 2; ++mb)
            #pragma unroll
            for (int nb = 0; nb < 8; ++nb)
                #pragma unroll
                for (int c = 0; c < 4; ++c) s[mb][nb][c] = 0.f;

        #pragma unroll
        for (int ks = 0; ks < 4; ++ks) {
            const uint32_t qx = ((2u * ks + l16) ^ l7) * 16;
            uint32_t ql0[4], ql1[4];
            ldsm4(ql0, smb + QL_OFF + qlrow + qx);
            ldsm4(ql1, smb + QL_OFF + qlrow + 2048 + qx);
            const uint32_t kx = ((2u * ks + l8) ^ l7) * 16;
            #pragma unroll
            for (int jp = 0; jp < 4; ++jp) {
                uint32_t kb[4];
                ldsm4(kb, sbase + KH_OFF + krowb + (uint32_t)jp * 2048 + kx);
                mma16816h(s[0][2 * jp],     qhr[0][ks], kb[0], kb[1]);
                mma16816h(s[0][2 * jp + 1], qhr[0][ks], kb[2], kb[3]);
                mma16816h(s[1][2 * jp],     qhr[1][ks], kb[0], kb[1]);
                mma16816h(s[1][2 * jp + 1], qhr[1][ks], kb[2], kb[3]);
                mma16816h(s[0][2 * jp],     ql0, kb[0], kb[1]);
                mma16816h(s[0][2 * jp + 1], ql0, kb[2], kb[3]);
                mma16816h(s[1][2 * jp],     ql1, kb[0], kb[1]);
                mma16816h(s[1][2 * jp + 1], ql1, kb[2], kb[3]);
            }
            #pragma unroll
            for (int jp = 0; jp < 4; ++jp) {
                uint32_t kb[4];
                ldsm4(kb, sbase + KL_OFF + krowb + (uint32_t)jp * 2048 + kx);
                mma16816h(s[0][2 * jp],     qhr[0][ks], kb[0], kb[1]);
                mma16816h(s[0][2 * jp + 1], qhr[0][ks], kb[2], kb[3]);
                mma16816h(s[1][2 * jp],     qhr[1][ks], kb[0], kb[1]);
                mma16816h(s[1][2 * jp + 1], qhr[1][ks], kb[2], kb[3]);
            }
        }

        // ---- online max (log2 domain) + P = 2^(s-m), pack fp16 ----
        uint32_t ph[2][8][2];
        #pragma unroll
        for (int mb = 0; mb < 2; ++mb) {
            float m0t = s[mb][0][0], m1t = s[mb][0][2];
            #pragma unroll
            for (int nb = 0; nb < 8; ++nb) {
                m0t = fmaxf(m0t, fmaxf(s[mb][nb][0], s[mb][nb][1]));
                m1t = fmaxf(m1t, fmaxf(s[mb][nb][2], s[mb][nb][3]));
            }
            m0t = fmaxf(m0t, __shfl_xor_sync(0xffffffffu, m0t, 1));
            m0t = fmaxf(m0t, __shfl_xor_sync(0xffffffffu, m0t, 2));
            m1t = fmaxf(m1t, __shfl_xor_sync(0xffffffffu, m1t, 1));
            m1t = fmaxf(m1t, __shfl_xor_sync(0xffffffffu, m1t, 2));

            const float m0n = fmaxf(m[mb][0], m0t);
            const float m1n = fmaxf(m[mb][1], m1t);
            const float a0 = ex2f(m[mb][0] - m0n);
            const float a1 = ex2f(m[mb][1] - m1n);
            m[mb][0] = m0n; m[mb][1] = m1n;
            lsum[mb][0] *= a0; lsum[mb][1] *= a1;
            #pragma unroll
            for (int nb = 0; nb < 8; ++nb) {
                o[mb][nb][0] *= a0; o[mb][nb][1] *= a0;
                o[mb][nb][2] *= a1; o[mb][nb][3] *= a1;
            }
            #pragma unroll
            for (int nb = 0; nb < 8; ++nb) {
                float e0 = ex2f(s[mb][nb][0] - m0n);
                float e1 = ex2f(s[mb][nb][1] - m0n);
                float e2 = ex2f(s[mb][nb][2] - m1n);
                float e3 = ex2f(s[mb][nb][3] - m1n);
                lsum[mb][0] += e0 + e1;
                lsum[mb][1] += e2 + e3;
                ph[mb][nb][0] = packh(e0, e1);
                ph[mb][nb][1] = packh(e2, e3);
            }
        }

        // ---- O += P V (single fp16 pass) ----
        #pragma unroll
        for (int kb = 0; kb < 4; ++kb) {
            uint32_t a0[4] = { ph[0][2 * kb][0], ph[0][2 * kb][1],
                               ph[0][2 * kb + 1][0], ph[0][2 * kb + 1][1] };
            uint32_t a1[4] = { ph[1][2 * kb][0], ph[1][2 * kb][1],
                               ph[1][2 * kb + 1][0], ph[1][2 * kb + 1][1] };
            const uint32_t vb_row = vrowb + (uint32_t)kb * 2048;
            #pragma unroll
            for (int np = 0; np < 4; ++np) {
                uint32_t vb[4];
                ldsm4t(vb, sbase + VH_OFF + vb_row + (((2u * np + l16) ^ l7) * 16));
                mma16816h(o[0][2 * np],     a0, vb[0], vb[1]);
                mma16816h(o[0][2 * np + 1], a0, vb[2], vb[3]);
                mma16816h(o[1][2 * np],     a1, vb[0], vb[1]);
                mma16816h(o[1][2 * np + 1], a1, vb[2], vb[3]);
            }
        }
    }

    // ---- epilogue: quad-reduce row sums, normalize, store ----
    #pragma unroll
    for (int mb = 0; mb < 2; ++mb) {
        #pragma unroll
        for (int h = 0; h < 2; ++h) {
            lsum[mb][h] += __shfl_xor_sync(0xffffffffu, lsum[mb][h], 1);
            lsum[mb][h] += __shfl_xor_sync(0xffffffffu, lsum[mb][h], 2);
        }
        const float inv0 = 1.f / lsum[mb][0];
        const float inv1 = 1.f / lsum[mb][1];
        const int row = q0 + wid * 32 + mb * 16 + (lane >> 2);
        float* op0 = O + ((size_t)b * SQ_ + row) * D_ + 2 * (lane & 3);
        float* op1 = op0 + 8 * D_;
        #pragma unroll
        for (int nb = 0; nb < 8; ++nb) {
            *(float2*)(op0 + 8 * nb) = make_float2(o[mb][nb][0] * inv0, o[mb][nb][1] * inv0);
            *(float2*)(op1 + 8 * nb) = make_float2(o[mb][nb][2] * inv1, o[mb][nb][3] * inv1);
        }
    }
}

extern "C" void kernel_launch(void* const* d_in, const int* in_sizes, int n_in,
                              void* d_out, int out_size)
{
    (void)in_sizes; (void)n_in; (void)out_size;
    const float* q = (const float*)d_in[0];
    const float* k = (const float*)d_in[1];
    const float* v = (const float*)d_in[2];
    float* o = (float*)d_out;

    dim3 sgrid(NT, B_);
    split_kv_kernel<<<sgrid, 256>>>(k, v);

    cudaFuncSetAttribute(attn_mma7_kernel,
                         cudaFuncAttributeMaxDynamicSharedMemorySize, SMEM_BYTES);
    dim3 grid(SQ_ / TQ, B_);
    attn_mma7_kernel<<<grid, 128, SMEM_BYTES>>>(q, o);
}

// round 10
// speedup vs baseline: 1.7552x; 1.0227x over previous
#include <cuda_runtime.h>
#include <cuda_fp16.h>
#include <cstdint>
#include <math.h>

// RingAttention out = softmax(Q K^T) V, B=32, SQ=1024, SKV=8192, D=64, fp32.
// R10: fp16 pipeline, M=32/warp. Softmax-phase compression:
//   - ex2.approx.f16x2 (one MUFU per 2 elements, cvt does the packing)
//   - row sums via ones-column MMA (lsum lives in a tensor accumulator)
//   - warp-vote rescale skip; mb-interleaved softmax/O for HMMA overlap

#define B_   32
#define SQ_  1024
#define SKV_ 8192
#define D_   64
#define TQ   128
#define TKV  64
#define NT   (SKV_ / TKV)

#define BLK_BYTES 24576
__device__ uint8_t gKV[(size_t)B_ * NT * BLK_BYTES];   // 96 MB scratch

#define QH_OFF 0
#define QL_OFF 16384
#define STG0   32768
#define KH_OFF 0
#define KL_OFF 8192
#define VH_OFF 16384
#define SMEM_BYTES (32768 + 2 * BLK_BYTES)   // 81920

__device__ __forceinline__ uint32_t smem_u32(const void* p) {
    uint32_t a;
    asm("{ .reg .u64 t; cvta.to.shared.u64 t, %1; cvt.u32.u64 %0, t; }" : "=r"(a) : "l"(p));
    return a;
}
__device__ __forceinline__ void ldsm4(uint32_t r[4], uint32_t a) {
    asm volatile("ldmatrix.sync.aligned.m8n8.x4.shared.b16 {%0,%1,%2,%3}, [%4];"
                 : "=r"(r[0]), "=r"(r[1]), "=r"(r[2]), "=r"(r[3]) : "r"(a));
}
__device__ __forceinline__ void ldsm4t(uint32_t r[4], uint32_t a) {
    asm volatile("ldmatrix.sync.aligned.m8n8.x4.trans.shared.b16 {%0,%1,%2,%3}, [%4];"
                 : "=r"(r[0]), "=r"(r[1]), "=r"(r[2]), "=r"(r[3]) : "r"(a));
}
__device__ __forceinline__ void mma16816h(float* c, const uint32_t* a, uint32_t b0, uint32_t b1) {
    asm volatile("mma.sync.aligned.m16n8k16.row.col.f32.f16.f16.f32 "
                 "{%0,%1,%2,%3}, {%4,%5,%6,%7}, {%8,%9}, {%0,%1,%2,%3};"
                 : "+f"(c[0]), "+f"(c[1]), "+f"(c[2]), "+f"(c[3])
                 : "r"(a[0]), "r"(a[1]), "r"(a[2]), "r"(a[3]), "r"(b0), "r"(b1));
}
__device__ __forceinline__ float ex2f(float x) {
    float r;
    asm("ex2.approx.f32 %0, %1;" : "=f"(r) : "f"(x));
    return r;
}
// P pair: pack (x,y) to f16x2 (x low), then 2^() elementwise
__device__ __forceinline__ uint32_t exp2pairh(float x, float y) {
    uint32_t d, r;
    asm("cvt.rn.f16x2.f32 %0, %1, %2;" : "=r"(d) : "f"(y), "f"(x));
    asm("ex2.approx.f16x2 %0, %1;" : "=r"(r) : "r"(d));
    return r;
}
__device__ __forceinline__ uint32_t packh(float x, float y) {
    __half2 h = __floats2half2_rn(x, y);
    return *reinterpret_cast<uint32_t*>(&h);
}
__device__ __forceinline__ void split2h(float x, float y, uint32_t& h, uint32_t& l) {
    __half2 hp = __floats2half2_rn(x, y);
    float rx = x - __half2float(__low2half(hp));
    float ry = y - __half2float(__high2half(hp));
    __half2 lp = __floats2half2_rn(rx, ry);
    h = *reinterpret_cast<uint32_t*>(&hp);
    l = *reinterpret_cast<uint32_t*>(&lp);
}
__device__ __forceinline__ void cvt8h(float4 a, float4 b, uint4& h, uint4& l) {
    split2h(a.x, a.y, h.x, l.x);
    split2h(a.z, a.w, h.y, l.y);
    split2h(b.x, b.y, h.z, l.z);
    split2h(b.z, b.w, h.w, l.w);
}
__device__ __forceinline__ uint4 cvt8h1(float4 a, float4 b) {
    uint4 h;
    h.x = packh(a.x, a.y);
    h.y = packh(a.z, a.w);
    h.z = packh(b.x, b.y);
    h.w = packh(b.z, b.w);
    return h;
}
#define CP_ASYNC16(dst, src) \
    asm volatile("cp.async.cg.shared.global [%0], [%1], 16;" :: "r"(dst), "l"(src))
#define CP_COMMIT() asm volatile("cp.async.commit_group;" ::: "memory")
#define CP_WAIT0()  asm volatile("cp.async.wait_group 0;" ::: "memory")

// ===================== kernel A: split K/V ======================
__global__ __launch_bounds__(256)
void split_kv_kernel(const float* __restrict__ K, const float* __restrict__ V)
{
    const int t = blockIdx.x;
    const int b = blockIdx.y;
    const int tid = threadIdx.x;

    const float* Kt = K + ((size_t)b * SKV_ + (size_t)t * TKV) * D_;
    const float* Vt = V + ((size_t)b * SKV_ + (size_t)t * TKV) * D_;
    uint8_t* blk = gKV + ((size_t)b * NT + t) * BLK_BYTES;

    #pragma unroll
    for (int uu = 0; uu < 2; ++uu) {
        const int u = tid + 256 * uu;
        const int r = u >> 3;
        const int c = u & 7;
        const uint32_t off = (uint32_t)r * 128 + (uint32_t)((c ^ (r & 7)) * 16);
        const float4* kp = (const float4*)(Kt + (size_t)r * D_ + c * 8);
        const float4* vp = (const float4*)(Vt + (size_t)r * D_ + c * 8);
        uint4 h, l;
        cvt8h(kp[0], kp[1], h, l);
        *(uint4*)(blk + KH_OFF + off) = h;
        *(uint4*)(blk + KL_OFF + off) = l;
        *(uint4*)(blk + VH_OFF + off) = cvt8h1(vp[0], vp[1]);
    }
}

// ===================== kernel B: attention ======================
__global__ __launch_bounds__(128, 2)
void attn_mma8_kernel(const float* __restrict__ Q, float* __restrict__ O)
{
    extern __shared__ char sm[];
    const uint32_t smb = smem_u32(sm);
    const int tid  = threadIdx.x;
    const int wid  = tid >> 5;
    const int lane = tid & 31;
    const uint32_t l7  = lane & 7;
    const uint32_t l8  = (lane >> 3) & 1;
    const uint32_t l15 = lane & 15;
    const uint32_t l16 = (uint32_t)lane >> 4;
    const int q0 = blockIdx.x * TQ;
    const int b  = blockIdx.y;

    const uint8_t* blk0 = gKV + (size_t)b * NT * BLK_BYTES;

    // ones-column B fragment (col 0 of an n8 block = 1, rest 0)
    const uint32_t bones = ((lane >> 2) == 0) ? 0x3C003C00u : 0u;

    // ---- prologue: Q * log2(e) -> smem fp16 hi/lo ----
    {
        const float4* qp = (const float4*)(Q + ((size_t)b * SQ_ + q0 + tid) * D_);
        const float LG2E = 1.4426950408889634f;
        #pragma unroll
        for (int c = 0; c < 8; ++c) {
            float4 f0 = qp[2 * c], f1 = qp[2 * c + 1];
            f0.x *= LG2E; f0.y *= LG2E; f0.z *= LG2E; f0.w *= LG2E;
            f1.x *= LG2E; f1.y *= LG2E; f1.z *= LG2E; f1.w *= LG2E;
            uint4 h, l;
            cvt8h(f0, f1, h, l);
            uint32_t x = (uint32_t)((c ^ (tid & 7)) * 16);
            *(uint4*)(sm + QH_OFF + tid * 128 + x) = h;
            *(uint4*)(sm + QL_OFF + tid * 128 + x) = l;
        }
    }
    __syncthreads();

    // hoist Qh fragments (Ql stays in smem)
    uint32_t qhr[2][4][4];
    #pragma unroll
    for (int mb = 0; mb < 2; ++mb)
        #pragma unroll
        for (int ks = 0; ks < 4; ++ks) {
            uint32_t a = smb + QH_OFF
                       + (uint32_t)(wid * 32 + mb * 16 + (int)l15) * 128
                       + (((2u * ks + l16) ^ l7) * 16);
            ldsm4(qhr[mb][ks], a);
        }

    // ---- stage 0: cp.async tile 0 ----
    {
        const uint32_t dst = smb + STG0 + (uint32_t)tid * 16;
        const uint8_t* src = blk0 + (size_t)tid * 16;
        #pragma unroll
        for (int i = 0; i < 12; ++i)
            CP_ASYNC16(dst + i * 2048, src + i * 2048);
        CP_COMMIT();
    }

    const uint32_t krowb = (8 * l16 + l7) * 128;
    const uint32_t vrowb = l15 * 128;
    const uint32_t qlrow = (uint32_t)(wid * 32 + (int)l15) * 128;

    float o[2][8][4];
    float oe[2][4];      // ones-column accumulator: oe[mb][0]=lsum row r, [2]=row r+8
    #pragma unroll
    for (int mb = 0; mb < 2; ++mb) {
        #pragma unroll
        for (int nb = 0; nb < 8; ++nb)
            #pragma unroll
            for (int c = 0; c < 4; ++c) o[mb][nb][c] = 0.f;
        #pragma unroll
        for (int c = 0; c < 4; ++c) oe[mb][c] = 0.f;
    }
    float m[2][2] = {{-1e30f, -1e30f}, {-1e30f, -1e30f}};

    for (int t = 0; t < NT; ++t) {
        CP_WAIT0();
        __syncthreads();

        if (t + 1 < NT) {
            const uint32_t dst = smb + STG0 + (uint32_t)(((t + 1) & 1) * BLK_BYTES)
                                 + (uint32_t)tid * 16;
            const uint8_t* src = blk0 + (size_t)(t + 1) * BLK_BYTES + (size_t)tid * 16;
            #pragma unroll
            for (int i = 0; i < 12; ++i)
                CP_ASYNC16(dst + i * 2048, src + i * 2048);
            CP_COMMIT();
        }

        const uint32_t sbase = smb + STG0 + (uint32_t)((t & 1) * BLK_BYTES);

        // ---- S (32x64 per warp): Qh Kh + Ql Kh + Qh Kl, fp32 accum ----
        float s[2][8][4];
        #pragma unroll
        for (int mb = 0; mb < 2; ++mb)
            #pragma unroll
            for (int nb = 0; nb < 8; ++nb)
                #pragma unroll
                for (int c = 0; c < 4; ++c) s[mb][nb][c] = 0.f;

        #pragma unroll
        for (int ks = 0; ks < 4; ++ks) {
            const uint32_t qx = ((2u * ks + l16) ^ l7) * 16;
            uint32_t ql0[4], ql1[4];
            ldsm4(ql0, smb + QL_OFF + qlrow + qx);
            ldsm4(ql1, smb + QL_OFF + qlrow + 2048 + qx);
            const uint32_t kx = ((2u * ks + l8) ^ l7) * 16;
            #pragma unroll
            for (int jp = 0; jp < 4; ++jp) {
                uint32_t kb[4];
                ldsm4(kb, sbase + KH_OFF + krowb + (uint32_t)jp * 2048 + kx);
                mma16816h(s[0][2 * jp],     qhr[0][ks], kb[0], kb[1]);
                mma16816h(s[0][2 * jp + 1], qhr[0][ks], kb[2], kb[3]);
                mma16816h(s[1][2 * jp],     qhr[1][ks], kb[0], kb[1]);
                mma16816h(s[1][2 * jp + 1], qhr[1][ks], kb[2], kb[3]);
                mma16816h(s[0][2 * jp],     ql0, kb[0], kb[1]);
                mma16816h(s[0][2 * jp + 1], ql0, kb[2], kb[3]);
                mma16816h(s[1][2 * jp],     ql1, kb[0], kb[1]);
                mma16816h(s[1][2 * jp + 1], ql1, kb[2], kb[3]);
            }
            #pragma unroll
            for (int jp = 0; jp < 4; ++jp) {
                uint32_t kb[4];
                ldsm4(kb, sbase + KL_OFF + krowb + (uint32_t)jp * 2048 + kx);
                mma16816h(s[0][2 * jp],     qhr[0][ks], kb[0], kb[1]);
                mma16816h(s[0][2 * jp + 1], qhr[0][ks], kb[2], kb[3]);
                mma16816h(s[1][2 * jp],     qhr[1][ks], kb[0], kb[1]);
                mma16816h(s[1][2 * jp + 1], qhr[1][ks], kb[2], kb[3]);
            }
        }

        // ---- per-mb: softmax then O-MMA (mb1 softmax overlaps mb0 HMMA) ----
        #pragma unroll
        for (int mb = 0; mb < 2; ++mb) {
            float m0t = s[mb][0][0], m1t = s[mb][0][2];
            #pragma unroll
            for (int nb = 0; nb < 8; ++nb) {
                m0t = fmaxf(m0t, fmaxf(s[mb][nb][0], s[mb][nb][1]));
                m1t = fmaxf(m1t, fmaxf(s[mb][nb][2], s[mb][nb][3]));
            }
            m0t = fmaxf(m0t, __shfl_xor_sync(0xffffffffu, m0t, 1));
            m0t = fmaxf(m0t, __shfl_xor_sync(0xffffffffu, m0t, 2));
            m1t = fmaxf(m1t, __shfl_xor_sync(0xffffffffu, m1t, 1));
            m1t = fmaxf(m1t, __shfl_xor_sync(0xffffffffu, m1t, 2));

            const float m0n = fmaxf(m[mb][0], m0t);
            const float m1n = fmaxf(m[mb][1], m1t);
            const float a0 = ex2f(m[mb][0] - m0n);
            const float a1 = ex2f(m[mb][1] - m1n);
            m[mb][0] = m0n; m[mb][1] = m1n;

            if (__any_sync(0xffffffffu, (a0 < 1.f) || (a1 < 1.f))) {
                #pragma unroll
                for (int nb = 0; nb < 8; ++nb) {
                    o[mb][nb][0] *= a0; o[mb][nb][1] *= a0;
                    o[mb][nb][2] *= a1; o[mb][nb][3] *= a1;
                }
                oe[mb][0] *= a0; oe[mb][1] *= a0;
                oe[mb][2] *= a1; oe[mb][3] *= a1;
            }

            // P = 2^(s - m): cvt-pack + f16x2 MUFU
            uint32_t ph[8][2];
            #pragma unroll
            for (int nb = 0; nb < 8; ++nb) {
                ph[nb][0] = exp2pairh(s[mb][nb][0] - m0n, s[mb][nb][1] - m0n);
                ph[nb][1] = exp2pairh(s[mb][nb][2] - m1n, s[mb][nb][3] - m1n);
            }

            // O += P V  (+ ones column accumulates row sums)
            #pragma unroll
            for (int kb = 0; kb < 4; ++kb) {
                uint32_t ah[4] = { ph[2 * kb][0], ph[2 * kb][1],
                                   ph[2 * kb + 1][0], ph[2 * kb + 1][1] };
                const uint32_t vb_row = vrowb + (uint32_t)kb * 2048;
                #pragma unroll
                for (int np = 0; np < 4; ++np) {
                    uint32_t vb[4];
                    ldsm4t(vb, sbase + VH_OFF + vb_row + (((2u * np + l16) ^ l7) * 16));
                    mma16816h(o[mb][2 * np],     ah, vb[0], vb[1]);
                    mma16816h(o[mb][2 * np + 1], ah, vb[2], vb[3]);
                }
                mma16816h(oe[mb], ah, bones, bones);
            }
        }
    }

    // ---- epilogue: lsum lives in oe (lanes with lane%4==0), broadcast, store ----
    #pragma unroll
    for (int mb = 0; mb < 2; ++mb) {
        const int srcl = lane & ~3;
        const float ls0 = __shfl_sync(0xffffffffu, oe[mb][0], srcl);
        const float ls1 = __shfl_sync(0xffffffffu, oe[mb][2], srcl);
        const float inv0 = 1.f / ls0;
        const float inv1 = 1.f / ls1;
        const int row = q0 + wid * 32 + mb * 16 + (lane >> 2);
        float* op0 = O + ((size_t)b * SQ_ + row) * D_ + 2 * (lane & 3);
        float* op1 = op0 + 8 * D_;
        #pragma unroll
        for (int nb = 0; nb < 8; ++nb) {
            *(float2*)(op0 + 8 * nb) = make_float2(o[mb][nb][0] * inv0, o[mb][nb][1] * inv0);
            *(float2*)(op1 + 8 * nb) = make_float2(o[mb][nb][2] * inv1, o[mb][nb][3] * inv1);
        }
    }
}

extern "C" void kernel_launch(void* const* d_in, const int* in_sizes, int n_in,
                              void* d_out, int out_size)
{
    (void)in_sizes; (void)n_in; (void)out_size;
    const float* q = (const float*)d_in[0];
    const float* k = (const float*)d_in[1];
    const float* v = (const float*)d_in[2];
    float* o = (float*)d_out;

    dim3 sgrid(NT, B_);
    split_kv_kernel<<<sgrid, 256>>>(k, v);

    cudaFuncSetAttribute(attn_mma8_kernel,
                         cudaFuncAttributeMaxDynamicSharedMemorySize, SMEM_BYTES);
    dim3 grid(SQ_ / TQ, B_);
    attn_mma8_kernel<<<grid, 128, SMEM_BYTES>>>(q, o);
}